// round 14
// baseline (speedup 1.0000x reference)
#include <cuda_runtime.h>
#include <cstdint>

// GaussianAgg: soft z-buffer aggregation via perturbed argmax.
// Shapes: zbuf/prob/mask [B,H,W,K=32] f32; noise [S=16,B,H,W,33]; out [B,H,W,33].
// ~345 MB HBM traffic (noise = 277 MB). One thread per pixel.
//
// R14 = R10 (best: 66.3us, DRAM 67%) with ONE structural change: per-WARP
// decoupled noise pipelines. Each warp owns a private 32-pixel chunk (4224 B)
// with its own double buffer; per-iteration sync is __syncwarp instead of two
// CTA-wide __syncthreads. R11/R12/R13 all showed the loss mechanism is
// barrier coupling (slowest-warp pacing + cross-CTA L1tex queue spread), not
// pipeline depth or CTA count.

#define GA_NSAMP 16
#define GA_K     32
#define GA_C     33            // K + background channel
#define GA_GAMMA 0.04f
#define GA_EPS   1e-10f
#define GA_TPB   128           // pixels per CTA
#define GA_WARPS (GA_TPB / 32)

#define CHUNK_FLOATS (GA_TPB * GA_C)        // 4224 floats = 16896 B per stage
#define CHUNK_F4     (CHUNK_FLOATS / 4)     // 1056
#define WCHUNK_FLOATS (32 * GA_C)           // 1056 floats = 4224 B per warp
#define WCHUNK_F4     (WCHUNK_FLOATS / 4)   // 264

__device__ __forceinline__ void cp_async16(uint32_t saddr, const void* gptr) {
    asm volatile("cp.async.ca.shared.global [%0], [%1], 16;\n"
                 :: "r"(saddr), "l"(gptr) : "memory");
}

__global__ __launch_bounds__(GA_TPB) void gaussian_agg_kernel(
    const float* __restrict__ zbuf,
    const float* __restrict__ zfar,
    const float* __restrict__ znear,
    const float* __restrict__ prob,
    const float* __restrict__ mask,
    const float* __restrict__ noise,
    float* __restrict__ out,
    int npix)
{
    // Layout: [stage 0 | stage 1], each stage = 4 contiguous warp slices of
    // 1056 floats. Stage 0 is also reused CTA-wide for the output epilogue.
    __shared__ __align__(16) float sbuf[2 * CHUNK_FLOATS];   // 33,792 B

    const int t    = threadIdx.x;
    const int w    = t >> 5;
    const int lane = t & 31;
    const int base = blockIdx.x * GA_TPB;
    const int p    = base + t;
    const bool active = (p < npix);
    const bool full   = (base + GA_TPB <= npix);             // uniform per CTA

    const size_t samp_stride = (size_t)npix * GA_C;
    const size_t chunk_off   = (size_t)base * GA_C;
    // This warp's slice of the noise chunk: pixels [base + w*32, base + w*32 + 32)
    const float* nsrc_w = noise + chunk_off + (size_t)(w * 32) * GA_C;
    const uint32_t sb   = (uint32_t)__cvta_generic_to_shared(sbuf);
    const uint32_t sbw  = sb + (uint32_t)(w * WCHUNK_FLOATS) * 4;   // warp slice, stage 0

    // ---- Per-warp prefetch of sample 0 BEFORE zmap compute (overlap) ----
    if (full) {
        #pragma unroll
        for (int i = 0; i < (WCHUNK_F4 + 31) / 32; i++) {
            int e = lane + i * 32;
            if (e < WCHUNK_F4) cp_async16(sbw + e * 16, nsrc_w + e * 4);
        }
        asm volatile("cp.async.commit_group;\n" ::: "memory");
    }

    const float zf = zfar[0];
    const float zn = znear[0];
    const float inv_range = 1.0f / (zf - zn);

    // ---- zmap: gamma*log(1e-12+prob) + z_inv - max(z_inv, EPS-floored) ----
    float zmap[GA_C];
    if (active) {
        const float4* zb4 = reinterpret_cast<const float4*>(zbuf + (size_t)p * GA_K);
        const float4* mk4 = reinterpret_cast<const float4*>(mask + (size_t)p * GA_K);
        float zmax = GA_EPS;
        #pragma unroll
        for (int i = 0; i < GA_K / 4; i++) {
            float4 z = zb4[i];
            float4 m = mk4[i];
            float a0 = (zf - z.x) * inv_range * m.x;
            float a1 = (zf - z.y) * inv_range * m.y;
            float a2 = (zf - z.z) * inv_range * m.z;
            float a3 = (zf - z.w) * inv_range * m.w;
            zmap[4*i + 0] = a0;
            zmap[4*i + 1] = a1;
            zmap[4*i + 2] = a2;
            zmap[4*i + 3] = a3;
            zmax = fmaxf(zmax, fmaxf(fmaxf(a0, a1), fmaxf(a2, a3)));
        }
        const float4* pr4 = reinterpret_cast<const float4*>(prob + (size_t)p * GA_K);
        #pragma unroll
        for (int i = 0; i < GA_K / 4; i++) {
            float4 q = pr4[i];
            zmap[4*i + 0] = GA_GAMMA * logf(1e-12f + q.x) + zmap[4*i + 0] - zmax;
            zmap[4*i + 1] = GA_GAMMA * logf(1e-12f + q.y) + zmap[4*i + 1] - zmax;
            zmap[4*i + 2] = GA_GAMMA * logf(1e-12f + q.z) + zmap[4*i + 2] - zmax;
            zmap[4*i + 3] = GA_GAMMA * logf(1e-12f + q.w) + zmap[4*i + 3] - zmax;
        }
        zmap[GA_K] = GA_EPS - zmax;
    }

    // ---- Per-sample perturbed argmax: per-warp double-buffered pipeline ----
    // No CTA-wide barriers in this loop. Each warp waits only on its own
    // cp.async groups; __syncwarp (memory-fenced) publishes staged data
    // across lanes. 20 independent warps/SM cover each other's latency.
    int idx[GA_NSAMP];
    #pragma unroll 1
    for (int s = 0; s < GA_NSAMP; s++) {
        const int cur = s & 1;

        if (full) {
            if (s + 1 < GA_NSAMP) {
                const float* src = nsrc_w + (size_t)(s + 1) * samp_stride;
                const uint32_t dst = sbw + ((s + 1) & 1) * (CHUNK_FLOATS * 4);
                #pragma unroll
                for (int i = 0; i < (WCHUNK_F4 + 31) / 32; i++) {
                    int e = lane + i * 32;
                    if (e < WCHUNK_F4) cp_async16(dst + e * 16, src + e * 4);
                }
                asm volatile("cp.async.commit_group;\n" ::: "memory");
                asm volatile("cp.async.wait_group 1;\n" ::: "memory");  // sample s ready
            } else {
                asm volatile("cp.async.wait_group 0;\n" ::: "memory");
            }
            __syncwarp();   // publish staged smem across lanes of this warp
        } else {
            // Tail CTA (never hit when npix % 128 == 0): CTA-wide sync staging.
            __syncthreads();
            const float* src = noise + (size_t)s * samp_stride + chunk_off;
            int elems = (npix - base > 0 ? npix - base : 0) * GA_C;
            for (int i = t; i < elems; i += GA_TPB) sbuf[cur * CHUNK_FLOATS + i] = src[i];
            __syncthreads();
        }

        if (active) {
            // Lane l reads word offset l*33 + c -> bank (l+c) mod 32: conflict-free.
            const float* ns = sbuf + cur * CHUNK_FLOATS + w * WCHUNK_FLOATS + lane * GA_C;
            // 4 independent chains over contiguous ranges; earlier-chain-wins merge
            // preserves exact first-max (strict >) tie-break semantics.
            float b0 = fmaf(GA_GAMMA, ns[0], zmap[0]);  int i0 = 0;
            #pragma unroll
            for (int c = 1; c <= 8; c++) {
                float v = fmaf(GA_GAMMA, ns[c], zmap[c]);
                if (v > b0) { b0 = v; i0 = c; }
            }
            float b1 = fmaf(GA_GAMMA, ns[9], zmap[9]);  int i1 = 9;
            #pragma unroll
            for (int c = 10; c <= 16; c++) {
                float v = fmaf(GA_GAMMA, ns[c], zmap[c]);
                if (v > b1) { b1 = v; i1 = c; }
            }
            float b2 = fmaf(GA_GAMMA, ns[17], zmap[17]); int i2 = 17;
            #pragma unroll
            for (int c = 18; c <= 24; c++) {
                float v = fmaf(GA_GAMMA, ns[c], zmap[c]);
                if (v > b2) { b2 = v; i2 = c; }
            }
            float b3 = fmaf(GA_GAMMA, ns[25], zmap[25]); int i3 = 25;
            #pragma unroll
            for (int c = 26; c <= 32; c++) {
                float v = fmaf(GA_GAMMA, ns[c], zmap[c]);
                if (v > b3) { b3 = v; i3 = c; }
            }
            if (b1 > b0) { b0 = b1; i0 = i1; }
            if (b2 > b0) { b0 = b2; i0 = i2; }
            if (b3 > b0) { b0 = b3; i0 = i3; }
            idx[s] = i0;
        }
        __syncwarp();   // lanes' reads done before next iter's prefetch overwrite
    }

    // ---- Mean of one-hots, staged through smem for coalesced stores ----
    __syncthreads();   // all warps done with noise buffers; reuse stage 0 CTA-wide
    if (active) {
        float* row = sbuf + t * GA_C;
        #pragma unroll
        for (int c = 0; c < GA_C; c++) {
            int cnt = 0;
            #pragma unroll
            for (int s = 0; s < GA_NSAMP; s++) cnt += (idx[s] == c);
            row[c] = (float)cnt * (1.0f / (float)GA_NSAMP);
        }
    }
    __syncthreads();

    float* dst = out + chunk_off;
    if (full) {
        const float4* s4 = reinterpret_cast<const float4*>(sbuf);
        float4*       d4 = reinterpret_cast<float4*>(dst);
        #pragma unroll
        for (int i = 0; i < (CHUNK_F4 + GA_TPB - 1) / GA_TPB; i++) {
            int e = t + i * GA_TPB;
            if (e < CHUNK_F4) d4[e] = s4[e];
        }
    } else {
        int elems = (npix - base > 0 ? npix - base : 0) * GA_C;
        for (int i = t; i < elems; i += GA_TPB) dst[i] = sbuf[i];
    }
}

extern "C" void kernel_launch(void* const* d_in, const int* in_sizes, int n_in,
                              void* d_out, int out_size)
{
    const float* zbuf  = (const float*)d_in[0];
    const float* zfar  = (const float*)d_in[1];
    const float* znear = (const float*)d_in[2];
    const float* prob  = (const float*)d_in[3];
    const float* mask  = (const float*)d_in[4];
    const float* noise = (const float*)d_in[5];
    float* out = (float*)d_out;

    int npix = in_sizes[0] / GA_K;   // B*H*W = 131072

    int blocks = (npix + GA_TPB - 1) / GA_TPB;
    gaussian_agg_kernel<<<blocks, GA_TPB>>>(zbuf, zfar, znear, prob, mask, noise,
                                            out, npix);
}

// round 15
// speedup vs baseline: 1.3337x; 1.3337x over previous
#include <cuda_runtime.h>
#include <cstdint>

// GaussianAgg: soft z-buffer aggregation via perturbed argmax.
// Shapes: zbuf/prob/mask [B,H,W,K=32] f32; noise [S=16,B,H,W,33]; out [B,H,W,33].
// ~345 MB HBM traffic. One thread per pixel.
//
// R15 = R10's noise loop byte-identical (66.3us best; R11-R14 proved every
// perturbation of it regresses) + coalesced smem staging of the zmap phase.
// R10's divergent float4 zmap loads cost 32 L1 wavefronts per LDG (768/warp,
// more than the whole noise stream); phase accounting says that's the missing
// ~33% of DRAM duty. Staged: 16 coalesced LDG.128/thread -> ~8x fewer
// wavefronts, zmap phase streams at full bandwidth.

#define GA_NSAMP 16
#define GA_K     32
#define GA_C     33            // K + background channel
#define GA_GAMMA 0.04f
#define GA_EPS   1e-10f
#define GA_TPB   128           // pixels per CTA

#define CHUNK_FLOATS (GA_TPB * GA_C)        // 4224 floats = 16896 B (also 128 rows x 33)
#define CHUNK_F4     (CHUNK_FLOATS / 4)     // 1056

__device__ __forceinline__ void cp_async16(uint32_t saddr, const void* gptr) {
    asm volatile("cp.async.ca.shared.global [%0], [%1], 16;\n"
                 :: "r"(saddr), "l"(gptr) : "memory");
}

__global__ __launch_bounds__(GA_TPB) void gaussian_agg_kernel(
    const float* __restrict__ zbuf,
    const float* __restrict__ zfar,
    const float* __restrict__ znear,
    const float* __restrict__ prob,
    const float* __restrict__ mask,
    const float* __restrict__ noise,
    float* __restrict__ out,
    int npix)
{
    __shared__ __align__(16) float sbuf[2 * CHUNK_FLOATS];   // 33,792 B

    const int t    = threadIdx.x;
    const int base = blockIdx.x * GA_TPB;
    const int p    = base + t;
    const bool active = (p < npix);
    const bool full   = (base + GA_TPB <= npix);             // uniform per CTA

    const size_t samp_stride = (size_t)npix * GA_C;
    const size_t chunk_off   = (size_t)base * GA_C;
    const float* nsrc        = noise + chunk_off;
    const uint32_t sb = (uint32_t)__cvta_generic_to_shared(sbuf);

    const float zf = zfar[0];
    const float zn = znear[0];
    const float inv_range = 1.0f / (zf - zn);

    float zmap[GA_C];

    if (full) {
        // ---- Coalesced staging: z_inv (computed inline) -> buf0, prob -> buf1.
        // Thread handles float4 index e = t + i*128 over the CTA's 4096-float
        // chunk: global row = e/8, col = (e%8)*4. Padded smem row stride = 33
        // words; STS banks (row + 4*(e%8)) all-distinct per warp, LDS banks
        // (t + c) mod 32 conflict-free.
        const float4* zb4 = reinterpret_cast<const float4*>(zbuf + (size_t)base * GA_K);
        const float4* mk4 = reinterpret_cast<const float4*>(mask + (size_t)base * GA_K);
        const float4* pr4 = reinterpret_cast<const float4*>(prob + (size_t)base * GA_K);
        #pragma unroll
        for (int i = 0; i < 8; i++) {
            int e = t + i * GA_TPB;
            float4 z = zb4[e];
            float4 m = mk4[e];
            float4 q = pr4[e];
            int row = e >> 3;
            int col = (e & 7) * 4;
            float* rz = sbuf + row * GA_C + col;
            rz[0] = (zf - z.x) * inv_range * m.x;
            rz[1] = (zf - z.y) * inv_range * m.y;
            rz[2] = (zf - z.z) * inv_range * m.z;
            rz[3] = (zf - z.w) * inv_range * m.w;
            float* rp = sbuf + CHUNK_FLOATS + row * GA_C + col;
            rp[0] = q.x; rp[1] = q.y; rp[2] = q.z; rp[3] = q.w;
        }
        __syncthreads();

        // ---- zmap from staged rows (conflict-free LDS) ----
        const float* zr = sbuf + t * GA_C;
        float zmax = GA_EPS;
        #pragma unroll
        for (int c = 0; c < GA_K; c++) {
            zmap[c] = zr[c];
            zmax = fmaxf(zmax, zmap[c]);
        }
        const float* pr = sbuf + CHUNK_FLOATS + t * GA_C;
        #pragma unroll
        for (int c = 0; c < GA_K; c++)
            zmap[c] = GA_GAMMA * logf(1e-12f + pr[c]) + zmap[c] - zmax;
        zmap[GA_K] = GA_EPS - zmax;
        __syncthreads();   // staging buffers free for the noise pipeline

        // ---- Prefetch noise sample 0 into buf0 ----
        #pragma unroll
        for (int i = 0; i < (CHUNK_F4 + GA_TPB - 1) / GA_TPB; i++) {
            int e = t + i * GA_TPB;
            if (e < CHUNK_F4) cp_async16(sb + e * 16, nsrc + e * 4);
        }
        asm volatile("cp.async.commit_group;\n" ::: "memory");
    } else if (active) {
        // Tail path (never hit when npix % 128 == 0): original direct loads.
        const float4* zb4 = reinterpret_cast<const float4*>(zbuf + (size_t)p * GA_K);
        const float4* mk4 = reinterpret_cast<const float4*>(mask + (size_t)p * GA_K);
        float zmax = GA_EPS;
        #pragma unroll
        for (int i = 0; i < GA_K / 4; i++) {
            float4 z = zb4[i];
            float4 m = mk4[i];
            float a0 = (zf - z.x) * inv_range * m.x;
            float a1 = (zf - z.y) * inv_range * m.y;
            float a2 = (zf - z.z) * inv_range * m.z;
            float a3 = (zf - z.w) * inv_range * m.w;
            zmap[4*i + 0] = a0; zmap[4*i + 1] = a1;
            zmap[4*i + 2] = a2; zmap[4*i + 3] = a3;
            zmax = fmaxf(zmax, fmaxf(fmaxf(a0, a1), fmaxf(a2, a3)));
        }
        const float4* pr4 = reinterpret_cast<const float4*>(prob + (size_t)p * GA_K);
        #pragma unroll
        for (int i = 0; i < GA_K / 4; i++) {
            float4 q = pr4[i];
            zmap[4*i + 0] = GA_GAMMA * logf(1e-12f + q.x) + zmap[4*i + 0] - zmax;
            zmap[4*i + 1] = GA_GAMMA * logf(1e-12f + q.y) + zmap[4*i + 1] - zmax;
            zmap[4*i + 2] = GA_GAMMA * logf(1e-12f + q.z) + zmap[4*i + 2] - zmax;
            zmap[4*i + 3] = GA_GAMMA * logf(1e-12f + q.w) + zmap[4*i + 3] - zmax;
        }
        zmap[GA_K] = GA_EPS - zmax;
    }

    // ---- Per-sample perturbed argmax: R10's loop, byte-identical ----
    int idx[GA_NSAMP];
    #pragma unroll 1
    for (int s = 0; s < GA_NSAMP; s++) {
        const int cur = s & 1;

        if (full) {
            if (s + 1 < GA_NSAMP) {
                const float* src = nsrc + (size_t)(s + 1) * samp_stride;
                const uint32_t dst = sb + ((s + 1) & 1) * (CHUNK_FLOATS * 4);
                #pragma unroll
                for (int i = 0; i < (CHUNK_F4 + GA_TPB - 1) / GA_TPB; i++) {
                    int e = t + i * GA_TPB;
                    if (e < CHUNK_F4) cp_async16(dst + e * 16, src + e * 4);
                }
                asm volatile("cp.async.commit_group;\n" ::: "memory");
                asm volatile("cp.async.wait_group 1;\n" ::: "memory");  // sample s ready
            } else {
                asm volatile("cp.async.wait_group 0;\n" ::: "memory");
            }
            __syncthreads();   // cross-thread visibility of staged data
        } else {
            __syncthreads();
            const float* src = nsrc + (size_t)s * samp_stride;
            int elems = (npix - base > 0 ? npix - base : 0) * GA_C;
            for (int i = t; i < elems; i += GA_TPB) sbuf[cur * CHUNK_FLOATS + i] = src[i];
            __syncthreads();
        }

        if (active) {
            // smem row: word-stride 33 across lanes -> bank (lane+c) mod 32, conflict-free.
            const float* ns = sbuf + cur * CHUNK_FLOATS + t * GA_C;
            // 4 independent chains; earlier-chain-wins merge preserves exact
            // first-max (strict >) tie-break semantics.
            float b0 = fmaf(GA_GAMMA, ns[0], zmap[0]);  int i0 = 0;
            #pragma unroll
            for (int c = 1; c <= 8; c++) {
                float v = fmaf(GA_GAMMA, ns[c], zmap[c]);
                if (v > b0) { b0 = v; i0 = c; }
            }
            float b1 = fmaf(GA_GAMMA, ns[9], zmap[9]);  int i1 = 9;
            #pragma unroll
            for (int c = 10; c <= 16; c++) {
                float v = fmaf(GA_GAMMA, ns[c], zmap[c]);
                if (v > b1) { b1 = v; i1 = c; }
            }
            float b2 = fmaf(GA_GAMMA, ns[17], zmap[17]); int i2 = 17;
            #pragma unroll
            for (int c = 18; c <= 24; c++) {
                float v = fmaf(GA_GAMMA, ns[c], zmap[c]);
                if (v > b2) { b2 = v; i2 = c; }
            }
            float b3 = fmaf(GA_GAMMA, ns[25], zmap[25]); int i3 = 25;
            #pragma unroll
            for (int c = 26; c <= 32; c++) {
                float v = fmaf(GA_GAMMA, ns[c], zmap[c]);
                if (v > b3) { b3 = v; i3 = c; }
            }
            if (b1 > b0) { b0 = b1; i0 = i1; }
            if (b2 > b0) { b0 = b2; i0 = i2; }
            if (b3 > b0) { b0 = b3; i0 = i3; }
            idx[s] = i0;
        }
        __syncthreads();   // reads done before this buffer is prefetch-overwritten
    }

    // ---- Mean of one-hots, staged through smem for coalesced stores ----
    if (active) {
        float* row = sbuf + t * GA_C;
        #pragma unroll
        for (int c = 0; c < GA_C; c++) {
            int cnt = 0;
            #pragma unroll
            for (int s = 0; s < GA_NSAMP; s++) cnt += (idx[s] == c);
            row[c] = (float)cnt * (1.0f / (float)GA_NSAMP);
        }
    }
    __syncthreads();

    float* dst = out + chunk_off;
    if (full) {
        const float4* s4 = reinterpret_cast<const float4*>(sbuf);
        float4*       d4 = reinterpret_cast<float4*>(dst);
        #pragma unroll
        for (int i = 0; i < (CHUNK_F4 + GA_TPB - 1) / GA_TPB; i++) {
            int e = t + i * GA_TPB;
            if (e < CHUNK_F4) d4[e] = s4[e];
        }
    } else {
        int elems = (npix - base > 0 ? npix - base : 0) * GA_C;
        for (int i = t; i < elems; i += GA_TPB) dst[i] = sbuf[i];
    }
}

extern "C" void kernel_launch(void* const* d_in, const int* in_sizes, int n_in,
                              void* d_out, int out_size)
{
    const float* zbuf  = (const float*)d_in[0];
    const float* zfar  = (const float*)d_in[1];
    const float* znear = (const float*)d_in[2];
    const float* prob  = (const float*)d_in[3];
    const float* mask  = (const float*)d_in[4];
    const float* noise = (const float*)d_in[5];
    float* out = (float*)d_out;

    int npix = in_sizes[0] / GA_K;   // B*H*W = 131072

    int blocks = (npix + GA_TPB - 1) / GA_TPB;
    gaussian_agg_kernel<<<blocks, GA_TPB>>>(zbuf, zfar, znear, prob, mask, noise,
                                            out, npix);
}